// round 10
// baseline (speedup 1.0000x reference)
#include <cuda_runtime.h>
#include <cuda_bf16.h>
#include <cstdint>
#include <math.h>

#define NNODES 20000
#define NEDGES 320000
#define NREL 3
#define FDIM 128
#define NEG_SLOPE 0.2f
#define CAP 96          // bucket capacity per (relation, dst)

// ---------------- scratch (static device globals; no allocation) ----------------
__device__ float g_f[(size_t)NREL * NNODES * FDIM];
__device__ float g_z[(size_t)NREL * NNODES * FDIM];
__device__ float g_el[NREL * NNODES * 2];
__device__ float g_er[NREL * NNODES * 2];
__device__ int   g_deg[NREL * NNODES];
__device__ int   g_bkt[(size_t)NREL * NNODES * CAP];
__device__ float g_wsum[2 * NREL];
// bf16 split operands
__device__ __nv_bfloat16 g_ahi[(size_t)NNODES * FDIM];
__device__ __nv_bfloat16 g_alo[(size_t)NNODES * FDIM];
__device__ __nv_bfloat16 g_whi[2 * NREL * FDIM * FDIM];   // [layer][r][n][k]
__device__ __nv_bfloat16 g_wlo[2 * NREL * FDIM * FDIM];

// ---------------- fused bucket build (hist + scatter, 4-edge ILP) ----------------
__global__ void k_build(const int* __restrict__ edges) {
    int r = blockIdx.y;
    int t = blockIdx.x * blockDim.x + threadIdx.x;
    if (t >= NEDGES / 4) return;
    const int4 s4 = *(const int4*)(edges + (size_t)(r * 2 + 0) * NEDGES + 4 * t);
    const int4 d4 = *(const int4*)(edges + (size_t)(r * 2 + 1) * NEDGES + 4 * t);
    int base = r * NNODES;
    int p0 = atomicAdd(&g_deg[base + d4.x], 1);
    int p1 = atomicAdd(&g_deg[base + d4.y], 1);
    int p2 = atomicAdd(&g_deg[base + d4.z], 1);
    int p3 = atomicAdd(&g_deg[base + d4.w], 1);
    g_bkt[(size_t)(base + d4.x) * CAP + p0] = s4.x;
    g_bkt[(size_t)(base + d4.y) * CAP + p1] = s4.y;
    g_bkt[(size_t)(base + d4.z) * CAP + p2] = s4.z;
    g_bkt[(size_t)(base + d4.w) * CAP + p3] = s4.w;
}

// ---------------- bf16 split conversion ----------------
__global__ void k_cvtA(const float* __restrict__ src,
                       __nv_bfloat16* __restrict__ hi, __nv_bfloat16* __restrict__ lo) {
    int i = blockIdx.x * blockDim.x + threadIdx.x;
    if (i >= NNODES * 32) return;
    float4 v = ((const float4*)src)[i];
    __nv_bfloat16 h0 = __float2bfloat16(v.x), h1 = __float2bfloat16(v.y);
    __nv_bfloat16 h2 = __float2bfloat16(v.z), h3 = __float2bfloat16(v.w);
    ((__nv_bfloat162*)hi)[2 * i]     = __nv_bfloat162(h0, h1);
    ((__nv_bfloat162*)hi)[2 * i + 1] = __nv_bfloat162(h2, h3);
    ((__nv_bfloat162*)lo)[2 * i]     = __nv_bfloat162(
        __float2bfloat16(v.x - __bfloat162float(h0)), __float2bfloat16(v.y - __bfloat162float(h1)));
    ((__nv_bfloat162*)lo)[2 * i + 1] = __nv_bfloat162(
        __float2bfloat16(v.z - __bfloat162float(h2)), __float2bfloat16(v.w - __bfloat162float(h3)));
}

__global__ void k_cvtW(const float* __restrict__ W1, const float* __restrict__ W2,
                       __nv_bfloat16* __restrict__ hi, __nv_bfloat16* __restrict__ lo) {
    int idx = blockIdx.x * blockDim.x + threadIdx.x;
    if (idx >= 2 * NREL * FDIM * FDIM) return;
    int l = idx / (NREL * FDIM * FDIM);
    int rem = idx - l * (NREL * FDIM * FDIM);
    int r = rem >> 14;
    int n = (rem >> 7) & 127, k = rem & 127;
    const float* W = l ? W2 : W1;
    float v = W[r * 16384 + k * 128 + n];
    __nv_bfloat16 h = __float2bfloat16(v);
    hi[idx] = h;
    lo[idx] = __float2bfloat16(v - __bfloat162float(h));
}

// ---------------- mma.sync GEMM (+ fused el/er epilogue) ----------------
#define ASTRIDE 136
#define TILEB  (128 * ASTRIDE)
#define TILEBYTES (TILEB * 2)

__device__ __forceinline__ uint32_t smem_u32(const void* p) {
    uint32_t a;
    asm("{ .reg .u64 t; cvta.to.shared.u64 t, %1; cvt.u32.u64 %0, t; }" : "=r"(a) : "l"(p));
    return a;
}
__device__ __forceinline__ void cp16(uint32_t dst, const void* src, int sz) {
    asm volatile("cp.async.cg.shared.global [%0], [%1], 16, %2;"
                 :: "r"(dst), "l"(src), "r"(sz));
}
__device__ __forceinline__ void ldsm_x4(uint32_t addr, uint32_t& r0, uint32_t& r1,
                                        uint32_t& r2, uint32_t& r3) {
    asm volatile("ldmatrix.sync.aligned.m8n8.x4.shared.b16 {%0,%1,%2,%3}, [%4];"
                 : "=r"(r0), "=r"(r1), "=r"(r2), "=r"(r3) : "r"(addr));
}
__device__ __forceinline__ void mma16816(float* c, uint32_t a0, uint32_t a1, uint32_t a2,
                                         uint32_t a3, uint32_t b0, uint32_t b1) {
    asm volatile(
        "mma.sync.aligned.m16n8k16.row.col.f32.bf16.bf16.f32 "
        "{%0,%1,%2,%3}, {%4,%5,%6,%7}, {%8,%9}, {%0,%1,%2,%3};"
        : "+f"(c[0]), "+f"(c[1]), "+f"(c[2]), "+f"(c[3])
        : "r"(a0), "r"(a1), "r"(a2), "r"(a3), "r"(b0), "r"(b1));
}

// 512 threads = 16 warps: 8 M-warps x 2 N-warps. Warp tile 16 rows x 64 cols.
__global__ void __launch_bounds__(512) k_gemm_mma(
    const __nv_bfloat16* __restrict__ ahi, const __nv_bfloat16* __restrict__ alo,
    const __nv_bfloat16* __restrict__ whi, const __nv_bfloat16* __restrict__ wlo,
    const float* __restrict__ alv, const float* __restrict__ arv,
    float* __restrict__ f_base, float* __restrict__ el_base, float* __restrict__ er_base) {
    extern __shared__ char smem[];
    __nv_bfloat16* Ah = (__nv_bfloat16*)smem;
    __nv_bfloat16* Al = Ah + TILEB;
    __nv_bfloat16* Bh = Al + TILEB;
    __nv_bfloat16* Bl = Bh + TILEB;
    float* s_al = (float*)(Bl + TILEB);
    float* s_ar = s_al + 128;
    uint32_t sb = smem_u32(smem);

    int tid = threadIdx.x;
    int wid = tid >> 5, lane = tid & 31;
    int wid_m = wid & 7, wid_n = wid >> 3;
    int r = blockIdx.y;
    int m0 = blockIdx.x * 128;

    float* f  = f_base  + (size_t)r * NNODES * FDIM;
    float* el = el_base + r * NNODES * 2;
    float* er = er_base + r * NNODES * 2;

    if (tid < 128) { s_al[tid] = alv[r * 128 + tid]; s_ar[tid] = arv[r * 128 + tid]; }

    // ---- cp.async fill ----
    const __nv_bfloat16* wh = whi + (size_t)r * 16384;
    const __nv_bfloat16* wl = wlo + (size_t)r * 16384;
    for (int c = tid; c < 2048; c += 512) {
        int row = c >> 4;
        int col = (c & 15) << 3;
        int gm = m0 + row;
        int sz = (gm < NNODES) ? 16 : 0;
        int gmc = (gm < NNODES) ? gm : (NNODES - 1);
        uint32_t soff = (uint32_t)(row * ASTRIDE + col) * 2;
        cp16(sb + soff,                 ahi + (size_t)gmc * 128 + col, sz);
        cp16(sb + TILEBYTES + soff,     alo + (size_t)gmc * 128 + col, sz);
        cp16(sb + 2 * TILEBYTES + soff, wh + row * 128 + col, 16);
        cp16(sb + 3 * TILEBYTES + soff, wl + row * 128 + col, 16);
    }
    asm volatile("cp.async.commit_group;");
    asm volatile("cp.async.wait_group 0;" ::: "memory");
    __syncthreads();

    // ---- MMA mainloop ----
    int m_base = wid_m * 16;
    int cb = wid_n * 64;
    float acc[8][4];
#pragma unroll
    for (int nt = 0; nt < 8; nt++)
#pragma unroll
        for (int j = 0; j < 4; j++) acc[nt][j] = 0.f;

    uint32_t a_row = (uint32_t)(m_base + (lane & 15));
    uint32_t a_colsel = (uint32_t)((lane >> 4) << 3);
    // B x4: lanes 0-7 tile nt (k-half 0), 8-15 (k-half 1), 16-23 tile nt+1, 24-31 (k-half 1)
    uint32_t b_row = (uint32_t)(cb + ((lane >> 4) & 1) * 8 + (lane & 7));
    uint32_t b_colsel = (uint32_t)(((lane >> 3) & 1) << 3);

#pragma unroll
    for (int t = 0; t < 3; t++) {
        const __nv_bfloat16* As = (t < 2) ? Ah : Al;
        const __nv_bfloat16* Bs = (t == 1) ? Bl : Bh;
        uint32_t a_base = smem_u32(As + a_row * ASTRIDE + a_colsel);
        uint32_t b_base = smem_u32(Bs + b_row * ASTRIDE + b_colsel);
#pragma unroll
        for (int kk = 0; kk < 8; kk++) {
            uint32_t a0, a1, a2, a3;
            ldsm_x4(a_base + kk * 32, a0, a1, a2, a3);
#pragma unroll
            for (int ntp = 0; ntp < 4; ntp++) {
                uint32_t b0, b1, b2, b3;
                ldsm_x4(b_base + (uint32_t)(ntp * 16 * ASTRIDE * 2) + kk * 32, b0, b1, b2, b3);
                mma16816(acc[2 * ntp],     a0, a1, a2, a3, b0, b1);
                mma16816(acc[2 * ntp + 1], a0, a1, a2, a3, b2, b3);
            }
        }
    }

    // ---- epilogue: fused el/er (head = wid_n, warp-local) + f stores ----
    int q = lane & 3;
    int r0 = m_base + (lane >> 2);
    int r1 = r0 + 8;
    int gm0 = m0 + r0, gm1 = m0 + r1;
    float elA = 0.f, erA = 0.f, elB = 0.f, erB = 0.f;
#pragma unroll
    for (int nt = 0; nt < 8; nt++) {
        int c0 = cb + nt * 8 + q * 2;
        float a0 = s_al[c0], a1 = s_al[c0 + 1];
        float b0 = s_ar[c0], b1 = s_ar[c0 + 1];
        elA += acc[nt][0] * a0 + acc[nt][1] * a1;
        elB += acc[nt][2] * a0 + acc[nt][3] * a1;
        erA += acc[nt][0] * b0 + acc[nt][1] * b1;
        erB += acc[nt][2] * b0 + acc[nt][3] * b1;
        if (gm0 < NNODES)
            *(float2*)(f + (size_t)gm0 * 128 + c0) = make_float2(acc[nt][0], acc[nt][1]);
        if (gm1 < NNODES)
            *(float2*)(f + (size_t)gm1 * 128 + c0) = make_float2(acc[nt][2], acc[nt][3]);
    }
#pragma unroll
    for (int o = 1; o <= 2; o <<= 1) {
        elA += __shfl_xor_sync(0xffffffffu, elA, o);
        erA += __shfl_xor_sync(0xffffffffu, erA, o);
        elB += __shfl_xor_sync(0xffffffffu, elB, o);
        erB += __shfl_xor_sync(0xffffffffu, erB, o);
    }
    if (q == 0) {
        if (gm0 < NNODES) { el[2 * gm0 + wid_n] = elA; er[2 * gm0 + wid_n] = erA; }
        if (gm1 < NNODES) { el[2 * gm1 + wid_n] = elB; er[2 * gm1 + wid_n] = erB; }
    }
}

#define SMEM_GEMM (4 * TILEBYTES + 2 * 128 * 4)

// ---------------- GAT aggregation + fused semantic score ----------------
// 4x unrolled edge loop: int4 src batch -> 4 el loads -> 4 f gathers (MLP ~8).
__global__ void __launch_bounds__(256) k_aggsc(
    const float* __restrict__ f_base, const float* __restrict__ el_base,
    const float* __restrict__ er_base, const float* __restrict__ bias_base,
    const float* __restrict__ w1, const float* __restrict__ bb,
    const float* __restrict__ w2, float* __restrict__ wsum,
    float* __restrict__ z_base, int do_relu) {
    int r = blockIdx.y;
    const float* f   = f_base  + (size_t)r * NNODES * FDIM;
    const float* el  = el_base + r * NNODES * 2;
    const float* er  = er_base + r * NNODES * 2;
    const float* bias = bias_base + r * 128;
    float* z = z_base + (size_t)r * NNODES * FDIM;

    __shared__ float s_w1[128 * 32];
    __shared__ float s_b1[32], s_w2[32];
    __shared__ float s_part[8];
    for (int i = threadIdx.x; i < 128 * 32; i += 256) s_w1[i] = w1[i];
    if (threadIdx.x < 32) { s_b1[threadIdx.x] = bb[threadIdx.x]; s_w2[threadIdx.x] = w2[threadIdx.x]; }
    __syncthreads();

    int wid = threadIdx.x >> 5, lane = threadIdx.x & 31;
    int n = blockIdx.x * 8 + wid;
    int deg = g_deg[r * NNODES + n];
    const int* bkt = &g_bkt[(size_t)(r * NNODES + n) * CAP];

    int myh = lane >> 4;
    float ermy = er[2 * n + myh];
    float4 acc = make_float4(0.f, 0.f, 0.f, 0.f);
    float den = 0.f;

    int i = 0;
    for (; i + 4 <= deg; i += 4) {
        int4 s4 = *(const int4*)(bkt + i);                  // 16B-aligned batch
        float e0 = el[2 * s4.x + myh];
        float e1 = el[2 * s4.y + myh];
        float e2 = el[2 * s4.z + myh];
        float e3 = el[2 * s4.w + myh];
        const float4* p0 = (const float4*)(f + (size_t)s4.x * 128 + lane * 4);
        const float4* p1 = (const float4*)(f + (size_t)s4.y * 128 + lane * 4);
        const float4* p2 = (const float4*)(f + (size_t)s4.z * 128 + lane * 4);
        const float4* p3 = (const float4*)(f + (size_t)s4.w * 128 + lane * 4);
        float4 f0 = *p0, f1 = *p1, f2 = *p2, f3 = *p3;      // 4 independent gathers
        e0 += ermy; e0 = e0 > 0.f ? e0 : NEG_SLOPE * e0;
        e1 += ermy; e1 = e1 > 0.f ? e1 : NEG_SLOPE * e1;
        e2 += ermy; e2 = e2 > 0.f ? e2 : NEG_SLOPE * e2;
        e3 += ermy; e3 = e3 > 0.f ? e3 : NEG_SLOPE * e3;
        float w0 = __expf(e0), w1v = __expf(e1), w2v = __expf(e2), w3 = __expf(e3);
        den += (w0 + w1v) + (w2v + w3);
        acc.x += w0 * f0.x + w1v * f1.x + w2v * f2.x + w3 * f3.x;
        acc.y += w0 * f0.y + w1v * f1.y + w2v * f2.y + w3 * f3.y;
        acc.z += w0 * f0.z + w1v * f1.z + w2v * f2.z + w3 * f3.z;
        acc.w += w0 * f0.w + w1v * f1.w + w2v * f2.w + w3 * f3.w;
    }
    for (; i < deg; i++) {
        int s = bkt[i];
        float e = el[2 * s + myh] + ermy;
        e = e > 0.f ? e : NEG_SLOPE * e;
        float w = __expf(e);
        den += w;
        float4 fv = *(const float4*)(f + (size_t)s * 128 + lane * 4);
        acc.x += w * fv.x; acc.y += w * fv.y; acc.z += w * fv.z; acc.w += w * fv.w;
    }

    float scale = 1.f / fmaxf(den, 1e-9f);
    float4 bv = *(const float4*)(bias + lane * 4);
    float4 o;
    o.x = acc.x * scale + bv.x;
    o.y = acc.y * scale + bv.y;
    o.z = acc.z * scale + bv.z;
    o.w = acc.w * scale + bv.w;
    if (do_relu) {
        o.x = fmaxf(o.x, 0.f); o.y = fmaxf(o.y, 0.f);
        o.z = fmaxf(o.z, 0.f); o.w = fmaxf(o.w, 0.f);
    }
    *(float4*)(z + (size_t)n * 128 + lane * 4) = o;

    // ---- fused semantic score ----
    float zr[4] = {o.x, o.y, o.z, o.w};
    float sacc = 0.f;
#pragma unroll
    for (int k = 0; k < 128; k++) {
        float zv = __shfl_sync(0xffffffffu, zr[k & 3], k >> 2);
        sacc += zv * s_w1[k * 32 + lane];
    }
    float t = tanhf(sacc + s_b1[lane]) * s_w2[lane];
#pragma unroll
    for (int oo = 16; oo; oo >>= 1) t += __shfl_xor_sync(0xffffffffu, t, oo);
    if (lane == 0) s_part[wid] = t;
    __syncthreads();
    if (threadIdx.x == 0) {
        float s = 0.f;
#pragma unroll
        for (int i2 = 0; i2 < 8; i2++) s += s_part[i2];
        atomicAdd(&wsum[r], s);
    }
}

// ---------------- combine (beta inline) ----------------
__device__ __forceinline__ void beta_from_wsum(const float* ws, float& b0, float& b1, float& b2) {
    float w0 = ws[0] / NNODES, w1 = ws[1] / NNODES, w2 = ws[2] / NNODES;
    float m = fmaxf(w0, fmaxf(w1, w2));
    float e0 = __expf(w0 - m), e1 = __expf(w1 - m), e2 = __expf(w2 - m);
    float s = e0 + e1 + e2;
    b0 = e0 / s; b1 = e1 / s; b2 = e2 / s;
}

__global__ void k_combine_bf(const float* __restrict__ z, const float* __restrict__ ws,
                             __nv_bfloat16* __restrict__ hi, __nv_bfloat16* __restrict__ lo) {
    int idx = blockIdx.x * blockDim.x + threadIdx.x;
    if (idx >= NNODES * 32) return;
    float b0, b1, b2;
    beta_from_wsum(ws, b0, b1, b2);
    float4 z0 = *(const float4*)(z + (size_t)idx * 4);
    float4 z1 = *(const float4*)(z + (size_t)NNODES * 128 + (size_t)idx * 4);
    float4 z2 = *(const float4*)(z + (size_t)2 * NNODES * 128 + (size_t)idx * 4);
    float vx = b0 * z0.x + b1 * z1.x + b2 * z2.x;
    float vy = b0 * z0.y + b1 * z1.y + b2 * z2.y;
    float vz = b0 * z0.z + b1 * z1.z + b2 * z2.z;
    float vw = b0 * z0.w + b1 * z1.w + b2 * z2.w;
    __nv_bfloat16 h0 = __float2bfloat16(vx), h1 = __float2bfloat16(vy);
    __nv_bfloat16 h2 = __float2bfloat16(vz), h3 = __float2bfloat16(vw);
    ((__nv_bfloat162*)hi)[2 * idx]     = __nv_bfloat162(h0, h1);
    ((__nv_bfloat162*)hi)[2 * idx + 1] = __nv_bfloat162(h2, h3);
    ((__nv_bfloat162*)lo)[2 * idx]     = __nv_bfloat162(
        __float2bfloat16(vx - __bfloat162float(h0)), __float2bfloat16(vy - __bfloat162float(h1)));
    ((__nv_bfloat162*)lo)[2 * idx + 1] = __nv_bfloat162(
        __float2bfloat16(vz - __bfloat162float(h2)), __float2bfloat16(vw - __bfloat162float(h3)));
}

__global__ void k_combine_f32(const float* __restrict__ z, const float* __restrict__ ws,
                              float* __restrict__ out) {
    int idx = blockIdx.x * blockDim.x + threadIdx.x;
    if (idx >= NNODES * 32) return;
    float b0, b1, b2;
    beta_from_wsum(ws, b0, b1, b2);
    float4 z0 = *(const float4*)(z + (size_t)idx * 4);
    float4 z1 = *(const float4*)(z + (size_t)NNODES * 128 + (size_t)idx * 4);
    float4 z2 = *(const float4*)(z + (size_t)2 * NNODES * 128 + (size_t)idx * 4);
    float4 o;
    o.x = b0 * z0.x + b1 * z1.x + b2 * z2.x;
    o.y = b0 * z0.y + b1 * z1.y + b2 * z2.y;
    o.z = b0 * z0.z + b1 * z1.z + b2 * z2.z;
    o.w = b0 * z0.w + b1 * z1.w + b2 * z2.w;
    *(float4*)(out + (size_t)idx * 4) = o;
}

// ---------------- launch ----------------
extern "C" void kernel_launch(void* const* d_in, const int* in_sizes, int n_in,
                              void* d_out, int out_size) {
    const float* x     = (const float*)d_in[0];
    const int*   edges = (const int*)d_in[1];
    const float* W1  = (const float*)d_in[2];
    const float* al1 = (const float*)d_in[3];
    const float* ar1 = (const float*)d_in[4];
    const float* b1  = (const float*)d_in[5];
    const float* W2  = (const float*)d_in[6];
    const float* al2 = (const float*)d_in[7];
    const float* ar2 = (const float*)d_in[8];
    const float* b2  = (const float*)d_in[9];
    const float* aw1 = (const float*)d_in[10];
    const float* ab1 = (const float*)d_in[11];
    const float* aw2 = (const float*)d_in[12];
    const float* bw1 = (const float*)d_in[13];
    const float* bb1 = (const float*)d_in[14];
    const float* bw2 = (const float*)d_in[15];
    float* out = (float*)d_out;

    float *p_f, *p_z, *p_el, *p_er, *p_ws;
    int *p_deg;
    __nv_bfloat16 *p_ahi, *p_alo, *p_whi, *p_wlo;
    cudaGetSymbolAddress((void**)&p_f,  g_f);
    cudaGetSymbolAddress((void**)&p_z,  g_z);
    cudaGetSymbolAddress((void**)&p_el, g_el);
    cudaGetSymbolAddress((void**)&p_er, g_er);
    cudaGetSymbolAddress((void**)&p_ws, g_wsum);
    cudaGetSymbolAddress((void**)&p_deg, g_deg);
    cudaGetSymbolAddress((void**)&p_ahi, g_ahi);
    cudaGetSymbolAddress((void**)&p_alo, g_alo);
    cudaGetSymbolAddress((void**)&p_whi, g_whi);
    cudaGetSymbolAddress((void**)&p_wlo, g_wlo);

    cudaFuncSetAttribute(k_gemm_mma, cudaFuncAttributeMaxDynamicSharedMemorySize, SMEM_GEMM);

    cudaMemsetAsync(p_deg, 0, NREL * NNODES * sizeof(int));
    cudaMemsetAsync(p_ws, 0, 2 * NREL * sizeof(float));
    k_build<<<dim3((NEDGES / 4 + 255) / 256, NREL), 256>>>(edges);
    k_cvtW<<<(2 * NREL * FDIM * FDIM + 255) / 256, 256>>>(W1, W2, p_whi, p_wlo);
    k_cvtA<<<(NNODES * 32 + 255) / 256, 256>>>(x, p_ahi, p_alo);

    const dim3 gemm_grid((NNODES + 127) / 128, NREL);
    const dim3 agg_grid(NNODES / 8, NREL);

    // ---- layer 1 ----
    k_gemm_mma<<<gemm_grid, 512, SMEM_GEMM>>>(p_ahi, p_alo, p_whi, p_wlo,
                                              al1, ar1, p_f, p_el, p_er);
    k_aggsc<<<agg_grid, 256>>>(p_f, p_el, p_er, b1, aw1, ab1, aw2, p_ws, p_z, 1);
    k_combine_bf<<<(NNODES * 32 + 255) / 256, 256>>>(p_z, p_ws, p_ahi, p_alo);

    // ---- layer 2 ----
    k_gemm_mma<<<gemm_grid, 512, SMEM_GEMM>>>(p_ahi, p_alo,
                                              p_whi + (size_t)NREL * FDIM * FDIM,
                                              p_wlo + (size_t)NREL * FDIM * FDIM,
                                              al2, ar2, p_f, p_el, p_er);
    k_aggsc<<<agg_grid, 256>>>(p_f, p_el, p_er, b2, bw1, bb1, bw2, p_ws + NREL, p_z, 0);
    k_combine_f32<<<(NNODES * 32 + 255) / 256, 256>>>(p_z, p_ws + NREL, out);
}

// round 11
// speedup vs baseline: 1.0307x; 1.0307x over previous
#include <cuda_runtime.h>
#include <cuda_bf16.h>
#include <cstdint>
#include <math.h>

#define NNODES 20000
#define NEDGES 320000
#define NREL 3
#define FDIM 128
#define NEG_SLOPE 0.2f
#define CAP 96          // bucket capacity per (relation, dst)

// ---------------- scratch (static device globals; no allocation) ----------------
__device__ float g_f[(size_t)NREL * NNODES * FDIM];
__device__ float g_z[(size_t)NREL * NNODES * FDIM];
__device__ float g_el[NREL * NNODES * 2];
__device__ float g_er[NREL * NNODES * 2];
__device__ int   g_deg[NREL * NNODES];
__device__ int   g_bkt[(size_t)NREL * NNODES * CAP];
__device__ float g_wsum[2 * NREL];
// bf16 split operands
__device__ __nv_bfloat16 g_ahi[(size_t)NNODES * FDIM];
__device__ __nv_bfloat16 g_alo[(size_t)NNODES * FDIM];
__device__ __nv_bfloat16 g_whi[2 * NREL * FDIM * FDIM];   // [layer][r][n][k]
__device__ __nv_bfloat16 g_wlo[2 * NREL * FDIM * FDIM];

// ---------------- fused bucket build (hist + scatter, 4-edge ILP) ----------------
__global__ void k_build(const int* __restrict__ edges) {
    int r = blockIdx.y;
    int t = blockIdx.x * blockDim.x + threadIdx.x;
    if (t >= NEDGES / 4) return;
    const int4 s4 = *(const int4*)(edges + (size_t)(r * 2 + 0) * NEDGES + 4 * t);
    const int4 d4 = *(const int4*)(edges + (size_t)(r * 2 + 1) * NEDGES + 4 * t);
    int base = r * NNODES;
    int p0 = atomicAdd(&g_deg[base + d4.x], 1);
    int p1 = atomicAdd(&g_deg[base + d4.y], 1);
    int p2 = atomicAdd(&g_deg[base + d4.z], 1);
    int p3 = atomicAdd(&g_deg[base + d4.w], 1);
    g_bkt[(size_t)(base + d4.x) * CAP + p0] = s4.x;
    g_bkt[(size_t)(base + d4.y) * CAP + p1] = s4.y;
    g_bkt[(size_t)(base + d4.z) * CAP + p2] = s4.z;
    g_bkt[(size_t)(base + d4.w) * CAP + p3] = s4.w;
}

// ---------------- bf16 split conversion ----------------
__global__ void k_cvtA(const float* __restrict__ src,
                       __nv_bfloat16* __restrict__ hi, __nv_bfloat16* __restrict__ lo) {
    int i = blockIdx.x * blockDim.x + threadIdx.x;
    if (i >= NNODES * 32) return;
    float4 v = ((const float4*)src)[i];
    __nv_bfloat16 h0 = __float2bfloat16(v.x), h1 = __float2bfloat16(v.y);
    __nv_bfloat16 h2 = __float2bfloat16(v.z), h3 = __float2bfloat16(v.w);
    ((__nv_bfloat162*)hi)[2 * i]     = __nv_bfloat162(h0, h1);
    ((__nv_bfloat162*)hi)[2 * i + 1] = __nv_bfloat162(h2, h3);
    ((__nv_bfloat162*)lo)[2 * i]     = __nv_bfloat162(
        __float2bfloat16(v.x - __bfloat162float(h0)), __float2bfloat16(v.y - __bfloat162float(h1)));
    ((__nv_bfloat162*)lo)[2 * i + 1] = __nv_bfloat162(
        __float2bfloat16(v.z - __bfloat162float(h2)), __float2bfloat16(v.w - __bfloat162float(h3)));
}

__global__ void k_cvtW(const float* __restrict__ W1, const float* __restrict__ W2,
                       __nv_bfloat16* __restrict__ hi, __nv_bfloat16* __restrict__ lo) {
    int idx = blockIdx.x * blockDim.x + threadIdx.x;
    if (idx >= 2 * NREL * FDIM * FDIM) return;
    int l = idx / (NREL * FDIM * FDIM);
    int rem = idx - l * (NREL * FDIM * FDIM);
    int r = rem >> 14;
    int n = (rem >> 7) & 127, k = rem & 127;
    const float* W = l ? W2 : W1;
    float v = W[r * 16384 + k * 128 + n];
    __nv_bfloat16 h = __float2bfloat16(v);
    hi[idx] = h;
    lo[idx] = __float2bfloat16(v - __bfloat162float(h));
}

// ---------------- mma.sync GEMM: A fragments direct-LDG, B in smem ----------------
#define ASTRIDE 136
#define TILEB  (128 * ASTRIDE)
#define TILEBYTES (TILEB * 2)

__device__ __forceinline__ uint32_t smem_u32(const void* p) {
    uint32_t a;
    asm("{ .reg .u64 t; cvta.to.shared.u64 t, %1; cvt.u32.u64 %0, t; }" : "=r"(a) : "l"(p));
    return a;
}
__device__ __forceinline__ void cp16(uint32_t dst, const void* src) {
    asm volatile("cp.async.cg.shared.global [%0], [%1], 16;" :: "r"(dst), "l"(src));
}
__device__ __forceinline__ void ldsm_x2(uint32_t addr, uint32_t& r0, uint32_t& r1) {
    asm volatile("ldmatrix.sync.aligned.m8n8.x2.shared.b16 {%0,%1}, [%2];"
                 : "=r"(r0), "=r"(r1) : "r"(addr));
}
__device__ __forceinline__ void mma16816(float* c, uint32_t a0, uint32_t a1, uint32_t a2,
                                         uint32_t a3, uint32_t b0, uint32_t b1) {
    asm volatile(
        "mma.sync.aligned.m16n8k16.row.col.f32.bf16.bf16.f32 "
        "{%0,%1,%2,%3}, {%4,%5,%6,%7}, {%8,%9}, {%0,%1,%2,%3};"
        : "+f"(c[0]), "+f"(c[1]), "+f"(c[2]), "+f"(c[3])
        : "r"(a0), "r"(a1), "r"(a2), "r"(a3), "r"(b0), "r"(b1));
}

// 512 threads = 16 warps: 8 M-warps x 2 N-warps. Warp tile 16 rows x 64 cols.
// D = Ah*Bh + Al*Bh + Ah*Bl accumulated in one acc; A frags via LDG.32 (clamped rows).
__global__ void __launch_bounds__(512) k_gemm_mma(
    const __nv_bfloat16* __restrict__ ahi, const __nv_bfloat16* __restrict__ alo,
    const __nv_bfloat16* __restrict__ whi, const __nv_bfloat16* __restrict__ wlo,
    const float* __restrict__ alv, const float* __restrict__ arv,
    float* __restrict__ f_base, float* __restrict__ el_base, float* __restrict__ er_base) {
    extern __shared__ char smem[];
    __nv_bfloat16* Bh = (__nv_bfloat16*)smem;
    __nv_bfloat16* Bl = Bh + TILEB;
    float* s_al = (float*)(Bl + TILEB);
    float* s_ar = s_al + 128;
    uint32_t sb = smem_u32(smem);

    int tid = threadIdx.x;
    int wid = tid >> 5, lane = tid & 31;
    int wid_m = wid & 7, wid_n = wid >> 3;
    int r = blockIdx.y;
    int m0 = blockIdx.x * 128;

    float* f  = f_base  + (size_t)r * NNODES * FDIM;
    float* el = el_base + r * NNODES * 2;
    float* er = er_base + r * NNODES * 2;

    if (tid < 128) { s_al[tid] = alv[r * 128 + tid]; s_ar[tid] = arv[r * 128 + tid]; }

    // ---- cp.async fill: B tiles only (Wh, Wl), 2048 16B-chunks each ----
    const __nv_bfloat16* wh = whi + (size_t)r * 16384;
    const __nv_bfloat16* wl = wlo + (size_t)r * 16384;
    for (int c = tid; c < 2048; c += 512) {
        int row = c >> 4;
        int col = (c & 15) << 3;
        uint32_t soff = (uint32_t)(row * ASTRIDE + col) * 2;
        cp16(sb + soff,             wh + row * 128 + col);
        cp16(sb + TILEBYTES + soff, wl + row * 128 + col);
    }
    asm volatile("cp.async.commit_group;");

    // A fragment pointers (rows clamped; stores guarded later)
    int m_base = wid_m * 16;
    int cb = wid_n * 64;
    int r0g = m0 + m_base + (lane >> 2);
    int r1g = r0g + 8;
    int r0c = (r0g < NNODES) ? r0g : 0;
    int r1c = (r1g < NNODES) ? r1g : 0;
    int coff = (lane & 3) * 2;
    const __nv_bfloat16* pAh0 = ahi + (size_t)r0c * 128 + coff;
    const __nv_bfloat16* pAh1 = ahi + (size_t)r1c * 128 + coff;
    const __nv_bfloat16* pAl0 = alo + (size_t)r0c * 128 + coff;
    const __nv_bfloat16* pAl1 = alo + (size_t)r1c * 128 + coff;

    float acc[8][4];
#pragma unroll
    for (int nt = 0; nt < 8; nt++)
#pragma unroll
        for (int j = 0; j < 4; j++) acc[nt][j] = 0.f;

    asm volatile("cp.async.wait_group 0;" ::: "memory");
    __syncthreads();

    uint32_t b_row = (uint32_t)(cb + (lane & 7));
    uint32_t b_colsel = (uint32_t)(((lane >> 3) & 1) << 3);
    uint32_t bh_base = smem_u32(Bh + b_row * ASTRIDE + b_colsel);
    uint32_t bl_base = smem_u32(Bl + b_row * ASTRIDE + b_colsel);

#pragma unroll
    for (int kk = 0; kk < 8; kk++) {
        int kc = kk * 16;
        uint32_t ah0 = *(const uint32_t*)(pAh0 + kc);
        uint32_t ah1 = *(const uint32_t*)(pAh1 + kc);
        uint32_t ah2 = *(const uint32_t*)(pAh0 + kc + 8);
        uint32_t ah3 = *(const uint32_t*)(pAh1 + kc + 8);
        uint32_t al0 = *(const uint32_t*)(pAl0 + kc);
        uint32_t al1 = *(const uint32_t*)(pAl1 + kc);
        uint32_t al2 = *(const uint32_t*)(pAl0 + kc + 8);
        uint32_t al3 = *(const uint32_t*)(pAl1 + kc + 8);
#pragma unroll
        for (int nt = 0; nt < 8; nt++) {
            uint32_t bo = (uint32_t)(nt * 8 * ASTRIDE * 2) + (uint32_t)kk * 32;
            uint32_t bh0, bh1, bl0, bl1;
            ldsm_x2(bh_base + bo, bh0, bh1);
            ldsm_x2(bl_base + bo, bl0, bl1);
            mma16816(acc[nt], ah0, ah1, ah2, ah3, bh0, bh1);
            mma16816(acc[nt], al0, al1, al2, al3, bh0, bh1);
            mma16816(acc[nt], ah0, ah1, ah2, ah3, bl0, bl1);
        }
    }

    // ---- epilogue: fused el/er (head = wid_n, warp-local) + f stores ----
    int q = lane & 3;
    int gm0 = r0g, gm1 = r1g;
    float elA = 0.f, erA = 0.f, elB = 0.f, erB = 0.f;
#pragma unroll
    for (int nt = 0; nt < 8; nt++) {
        int c0 = cb + nt * 8 + q * 2;
        float a0 = s_al[c0], a1 = s_al[c0 + 1];
        float b0 = s_ar[c0], b1 = s_ar[c0 + 1];
        elA += acc[nt][0] * a0 + acc[nt][1] * a1;
        elB += acc[nt][2] * a0 + acc[nt][3] * a1;
        erA += acc[nt][0] * b0 + acc[nt][1] * b1;
        erB += acc[nt][2] * b0 + acc[nt][3] * b1;
        if (gm0 < NNODES)
            *(float2*)(f + (size_t)gm0 * 128 + c0) = make_float2(acc[nt][0], acc[nt][1]);
        if (gm1 < NNODES)
            *(float2*)(f + (size_t)gm1 * 128 + c0) = make_float2(acc[nt][2], acc[nt][3]);
    }
#pragma unroll
    for (int o = 1; o <= 2; o <<= 1) {
        elA += __shfl_xor_sync(0xffffffffu, elA, o);
        erA += __shfl_xor_sync(0xffffffffu, erA, o);
        elB += __shfl_xor_sync(0xffffffffu, elB, o);
        erB += __shfl_xor_sync(0xffffffffu, erB, o);
    }
    if (q == 0) {
        if (gm0 < NNODES) { el[2 * gm0 + wid_n] = elA; er[2 * gm0 + wid_n] = erA; }
        if (gm1 < NNODES) { el[2 * gm1 + wid_n] = elB; er[2 * gm1 + wid_n] = erB; }
    }
}

#define SMEM_GEMM (2 * TILEBYTES + 2 * 128 * 4)

// ---------------- GAT aggregation + fused semantic score (round-8 serial loop) ----------------
__global__ void __launch_bounds__(256) k_aggsc(
    const float* __restrict__ f_base, const float* __restrict__ el_base,
    const float* __restrict__ er_base, const float* __restrict__ bias_base,
    const float* __restrict__ w1, const float* __restrict__ bb,
    const float* __restrict__ w2, float* __restrict__ wsum,
    float* __restrict__ z_base, int do_relu) {
    int r = blockIdx.y;
    const float* f   = f_base  + (size_t)r * NNODES * FDIM;
    const float* el  = el_base + r * NNODES * 2;
    const float* er  = er_base + r * NNODES * 2;
    const float* bias = bias_base + r * 128;
    float* z = z_base + (size_t)r * NNODES * FDIM;

    __shared__ float s_w1[128 * 32];
    __shared__ float s_b1[32], s_w2[32];
    __shared__ float s_part[8];
    for (int i = threadIdx.x; i < 128 * 32; i += 256) s_w1[i] = w1[i];
    if (threadIdx.x < 32) { s_b1[threadIdx.x] = bb[threadIdx.x]; s_w2[threadIdx.x] = w2[threadIdx.x]; }
    __syncthreads();

    int wid = threadIdx.x >> 5, lane = threadIdx.x & 31;
    int n = blockIdx.x * 8 + wid;
    int deg = g_deg[r * NNODES + n];
    const int* bkt = &g_bkt[(size_t)(r * NNODES + n) * CAP];

    // scores are O(1): exp(e)/sum(exp(e)) == softmax (max subtraction is a no-op here)
    int myh = lane >> 4;
    float ermy = er[2 * n + myh];
    float4 acc = make_float4(0.f, 0.f, 0.f, 0.f);
    float den = 0.f;
    for (int i = 0; i < deg; i++) {
        int s = bkt[i];
        float e = el[2 * s + myh] + ermy;
        e = e > 0.f ? e : NEG_SLOPE * e;
        float w = __expf(e);
        den += w;
        float4 fv = *(const float4*)(f + (size_t)s * 128 + lane * 4);
        acc.x += w * fv.x; acc.y += w * fv.y; acc.z += w * fv.z; acc.w += w * fv.w;
    }
    float scale = 1.f / fmaxf(den, 1e-9f);
    float4 bv = *(const float4*)(bias + lane * 4);
    float4 o;
    o.x = acc.x * scale + bv.x;
    o.y = acc.y * scale + bv.y;
    o.z = acc.z * scale + bv.z;
    o.w = acc.w * scale + bv.w;
    if (do_relu) {
        o.x = fmaxf(o.x, 0.f); o.y = fmaxf(o.y, 0.f);
        o.z = fmaxf(o.z, 0.f); o.w = fmaxf(o.w, 0.f);
    }
    *(float4*)(z + (size_t)n * 128 + lane * 4) = o;

    // ---- fused semantic score ----
    float zr[4] = {o.x, o.y, o.z, o.w};
    float sacc = 0.f;
#pragma unroll
    for (int k = 0; k < 128; k++) {
        float zv = __shfl_sync(0xffffffffu, zr[k & 3], k >> 2);
        sacc += zv * s_w1[k * 32 + lane];
    }
    float t = tanhf(sacc + s_b1[lane]) * s_w2[lane];
#pragma unroll
    for (int oo = 16; oo; oo >>= 1) t += __shfl_xor_sync(0xffffffffu, t, oo);
    if (lane == 0) s_part[wid] = t;
    __syncthreads();
    if (threadIdx.x == 0) {
        float s = 0.f;
#pragma unroll
        for (int i2 = 0; i2 < 8; i2++) s += s_part[i2];
        atomicAdd(&wsum[r], s);
    }
}

// ---------------- combine (beta inline) ----------------
__device__ __forceinline__ void beta_from_wsum(const float* ws, float& b0, float& b1, float& b2) {
    float w0 = ws[0] / NNODES, w1 = ws[1] / NNODES, w2 = ws[2] / NNODES;
    float m = fmaxf(w0, fmaxf(w1, w2));
    float e0 = __expf(w0 - m), e1 = __expf(w1 - m), e2 = __expf(w2 - m);
    float s = e0 + e1 + e2;
    b0 = e0 / s; b1 = e1 / s; b2 = e2 / s;
}

__global__ void k_combine_bf(const float* __restrict__ z, const float* __restrict__ ws,
                             __nv_bfloat16* __restrict__ hi, __nv_bfloat16* __restrict__ lo) {
    int idx = blockIdx.x * blockDim.x + threadIdx.x;
    if (idx >= NNODES * 32) return;
    float b0, b1, b2;
    beta_from_wsum(ws, b0, b1, b2);
    float4 z0 = *(const float4*)(z + (size_t)idx * 4);
    float4 z1 = *(const float4*)(z + (size_t)NNODES * 128 + (size_t)idx * 4);
    float4 z2 = *(const float4*)(z + (size_t)2 * NNODES * 128 + (size_t)idx * 4);
    float vx = b0 * z0.x + b1 * z1.x + b2 * z2.x;
    float vy = b0 * z0.y + b1 * z1.y + b2 * z2.y;
    float vz = b0 * z0.z + b1 * z1.z + b2 * z2.z;
    float vw = b0 * z0.w + b1 * z1.w + b2 * z2.w;
    __nv_bfloat16 h0 = __float2bfloat16(vx), h1 = __float2bfloat16(vy);
    __nv_bfloat16 h2 = __float2bfloat16(vz), h3 = __float2bfloat16(vw);
    ((__nv_bfloat162*)hi)[2 * idx]     = __nv_bfloat162(h0, h1);
    ((__nv_bfloat162*)hi)[2 * idx + 1] = __nv_bfloat162(h2, h3);
    ((__nv_bfloat162*)lo)[2 * idx]     = __nv_bfloat162(
        __float2bfloat16(vx - __bfloat162float(h0)), __float2bfloat16(vy - __bfloat162float(h1)));
    ((__nv_bfloat162*)lo)[2 * idx + 1] = __nv_bfloat162(
        __float2bfloat16(vz - __bfloat162float(h2)), __float2bfloat16(vw - __bfloat162float(h3)));
}

__global__ void k_combine_f32(const float* __restrict__ z, const float* __restrict__ ws,
                              float* __restrict__ out) {
    int idx = blockIdx.x * blockDim.x + threadIdx.x;
    if (idx >= NNODES * 32) return;
    float b0, b1, b2;
    beta_from_wsum(ws, b0, b1, b2);
    float4 z0 = *(const float4*)(z + (size_t)idx * 4);
    float4 z1 = *(const float4*)(z + (size_t)NNODES * 128 + (size_t)idx * 4);
    float4 z2 = *(const float4*)(z + (size_t)2 * NNODES * 128 + (size_t)idx * 4);
    float4 o;
    o.x = b0 * z0.x + b1 * z1.x + b2 * z2.x;
    o.y = b0 * z0.y + b1 * z1.y + b2 * z2.y;
    o.z = b0 * z0.z + b1 * z1.z + b2 * z2.z;
    o.w = b0 * z0.w + b1 * z1.w + b2 * z2.w;
    *(float4*)(out + (size_t)idx * 4) = o;
}

// ---------------- launch ----------------
extern "C" void kernel_launch(void* const* d_in, const int* in_sizes, int n_in,
                              void* d_out, int out_size) {
    const float* x     = (const float*)d_in[0];
    const int*   edges = (const int*)d_in[1];
    const float* W1  = (const float*)d_in[2];
    const float* al1 = (const float*)d_in[3];
    const float* ar1 = (const float*)d_in[4];
    const float* b1  = (const float*)d_in[5];
    const float* W2  = (const float*)d_in[6];
    const float* al2 = (const float*)d_in[7];
    const float* ar2 = (const float*)d_in[8];
    const float* b2  = (const float*)d_in[9];
    const float* aw1 = (const float*)d_in[10];
    const float* ab1 = (const float*)d_in[11];
    const float* aw2 = (const float*)d_in[12];
    const float* bw1 = (const float*)d_in[13];
    const float* bb1 = (const float*)d_in[14];
    const float* bw2 = (const float*)d_in[15];
    float* out = (float*)d_out;

    float *p_f, *p_z, *p_el, *p_er, *p_ws;
    int *p_deg;
    __nv_bfloat16 *p_ahi, *p_alo, *p_whi, *p_wlo;
    cudaGetSymbolAddress((void**)&p_f,  g_f);
    cudaGetSymbolAddress((void**)&p_z,  g_z);
    cudaGetSymbolAddress((void**)&p_el, g_el);
    cudaGetSymbolAddress((void**)&p_er, g_er);
    cudaGetSymbolAddress((void**)&p_ws, g_wsum);
    cudaGetSymbolAddress((void**)&p_deg, g_deg);
    cudaGetSymbolAddress((void**)&p_ahi, g_ahi);
    cudaGetSymbolAddress((void**)&p_alo, g_alo);
    cudaGetSymbolAddress((void**)&p_whi, g_whi);
    cudaGetSymbolAddress((void**)&p_wlo, g_wlo);

    cudaFuncSetAttribute(k_gemm_mma, cudaFuncAttributeMaxDynamicSharedMemorySize, SMEM_GEMM);

    cudaMemsetAsync(p_deg, 0, NREL * NNODES * sizeof(int));
    cudaMemsetAsync(p_ws, 0, 2 * NREL * sizeof(float));
    k_build<<<dim3((NEDGES / 4 + 255) / 256, NREL), 256>>>(edges);
    k_cvtW<<<(2 * NREL * FDIM * FDIM + 255) / 256, 256>>>(W1, W2, p_whi, p_wlo);
    k_cvtA<<<(NNODES * 32 + 255) / 256, 256>>>(x, p_ahi, p_alo);

    const dim3 gemm_grid((NNODES + 127) / 128, NREL);
    const dim3 agg_grid(NNODES / 8, NREL);

    // ---- layer 1 ----
    k_gemm_mma<<<gemm_grid, 512, SMEM_GEMM>>>(p_ahi, p_alo, p_whi, p_wlo,
                                              al1, ar1, p_f, p_el, p_er);
    k_aggsc<<<agg_grid, 256>>>(p_f, p_el, p_er, b1, aw1, ab1, aw2, p_ws, p_z, 1);
    k_combine_bf<<<(NNODES * 32 + 255) / 256, 256>>>(p_z, p_ws, p_ahi, p_alo);

    // ---- layer 2 ----
    k_gemm_mma<<<gemm_grid, 512, SMEM_GEMM>>>(p_ahi, p_alo,
                                              p_whi + (size_t)NREL * FDIM * FDIM,
                                              p_wlo + (size_t)NREL * FDIM * FDIM,
                                              al2, ar2, p_f, p_el, p_er);
    k_aggsc<<<agg_grid, 256>>>(p_f, p_el, p_er, b2, bw1, bb1, bw2, p_ws + NREL, p_z, 0);
    k_combine_f32<<<(NNODES * 32 + 255) / 256, 256>>>(p_z, p_ws + NREL, out);
}

// round 13
// speedup vs baseline: 1.0780x; 1.0459x over previous
#include <cuda_runtime.h>
#include <cuda_bf16.h>
#include <cstdint>
#include <math.h>

#define NNODES 20000
#define NEDGES 320000
#define NREL 3
#define FDIM 128
#define NEG_SLOPE 0.2f
#define CAP 96          // bucket capacity per (relation, dst)

// ---------------- scratch (static device globals; no allocation) ----------------
__device__ float g_f[(size_t)NREL * NNODES * FDIM];
__device__ float g_z[(size_t)NREL * NNODES * FDIM];
__device__ float g_el[NREL * NNODES * 2];
__device__ float g_er[NREL * NNODES * 2];
__device__ int   g_deg[NREL * NNODES];
__device__ int   g_bkt[(size_t)NREL * NNODES * CAP];
__device__ float g_wsum[2 * NREL];
// bf16 split operands
__device__ __nv_bfloat16 g_ahi[(size_t)NNODES * FDIM];
__device__ __nv_bfloat16 g_alo[(size_t)NNODES * FDIM];
__device__ __nv_bfloat16 g_whi[2 * NREL * FDIM * FDIM];   // [layer][r][n][k]
__device__ __nv_bfloat16 g_wlo[2 * NREL * FDIM * FDIM];

// ---------------- fused bucket build (hist + scatter, 4-edge ILP) ----------------
__global__ void k_build(const int* __restrict__ edges) {
    int r = blockIdx.y;
    int t = blockIdx.x * blockDim.x + threadIdx.x;
    if (t >= NEDGES / 4) return;
    const int4 s4 = *(const int4*)(edges + (size_t)(r * 2 + 0) * NEDGES + 4 * t);
    const int4 d4 = *(const int4*)(edges + (size_t)(r * 2 + 1) * NEDGES + 4 * t);
    int base = r * NNODES;
    int p0 = atomicAdd(&g_deg[base + d4.x], 1);
    int p1 = atomicAdd(&g_deg[base + d4.y], 1);
    int p2 = atomicAdd(&g_deg[base + d4.z], 1);
    int p3 = atomicAdd(&g_deg[base + d4.w], 1);
    g_bkt[(size_t)(base + d4.x) * CAP + p0] = s4.x;
    g_bkt[(size_t)(base + d4.y) * CAP + p1] = s4.y;
    g_bkt[(size_t)(base + d4.z) * CAP + p2] = s4.z;
    g_bkt[(size_t)(base + d4.w) * CAP + p3] = s4.w;
}

// ---------------- bf16 split conversion ----------------
__global__ void k_cvtA(const float* __restrict__ src,
                       __nv_bfloat16* __restrict__ hi, __nv_bfloat16* __restrict__ lo) {
    int i = blockIdx.x * blockDim.x + threadIdx.x;
    if (i >= NNODES * 32) return;
    float4 v = ((const float4*)src)[i];
    __nv_bfloat16 h0 = __float2bfloat16(v.x), h1 = __float2bfloat16(v.y);
    __nv_bfloat16 h2 = __float2bfloat16(v.z), h3 = __float2bfloat16(v.w);
    ((__nv_bfloat162*)hi)[2 * i]     = __nv_bfloat162(h0, h1);
    ((__nv_bfloat162*)hi)[2 * i + 1] = __nv_bfloat162(h2, h3);
    ((__nv_bfloat162*)lo)[2 * i]     = __nv_bfloat162(
        __float2bfloat16(v.x - __bfloat162float(h0)), __float2bfloat16(v.y - __bfloat162float(h1)));
    ((__nv_bfloat162*)lo)[2 * i + 1] = __nv_bfloat162(
        __float2bfloat16(v.z - __bfloat162float(h2)), __float2bfloat16(v.w - __bfloat162float(h3)));
}

__global__ void k_cvtW(const float* __restrict__ W1, const float* __restrict__ W2,
                       __nv_bfloat16* __restrict__ hi, __nv_bfloat16* __restrict__ lo) {
    int idx = blockIdx.x * blockDim.x + threadIdx.x;
    if (idx >= 2 * NREL * FDIM * FDIM) return;
    int l = idx / (NREL * FDIM * FDIM);
    int rem = idx - l * (NREL * FDIM * FDIM);
    int r = rem >> 14;
    int n = (rem >> 7) & 127, k = rem & 127;
    const float* W = l ? W2 : W1;
    float v = W[r * 16384 + k * 128 + n];
    __nv_bfloat16 h = __float2bfloat16(v);
    hi[idx] = h;
    lo[idx] = __float2bfloat16(v - __bfloat162float(h));
}

// ---------------- mma.sync GEMM (round-8 version, verbatim) ----------------
#define ASTRIDE 136
#define TILEB  (128 * ASTRIDE)
#define TILEBYTES (TILEB * 2)

__device__ __forceinline__ uint32_t smem_u32(const void* p) {
    uint32_t a;
    asm("{ .reg .u64 t; cvta.to.shared.u64 t, %1; cvt.u32.u64 %0, t; }" : "=r"(a) : "l"(p));
    return a;
}
__device__ __forceinline__ void cp16(uint32_t dst, const void* src, int sz) {
    asm volatile("cp.async.cg.shared.global [%0], [%1], 16, %2;"
                 :: "r"(dst), "l"(src), "r"(sz));
}
__device__ __forceinline__ void ldsm_x4(uint32_t addr, uint32_t& r0, uint32_t& r1,
                                        uint32_t& r2, uint32_t& r3) {
    asm volatile("ldmatrix.sync.aligned.m8n8.x4.shared.b16 {%0,%1,%2,%3}, [%4];"
                 : "=r"(r0), "=r"(r1), "=r"(r2), "=r"(r3) : "r"(addr));
}
__device__ __forceinline__ void ldsm_x2(uint32_t addr, uint32_t& r0, uint32_t& r1) {
    asm volatile("ldmatrix.sync.aligned.m8n8.x2.shared.b16 {%0,%1}, [%2];"
                 : "=r"(r0), "=r"(r1) : "r"(addr));
}
__device__ __forceinline__ void mma16816(float* c, uint32_t a0, uint32_t a1, uint32_t a2,
                                         uint32_t a3, uint32_t b0, uint32_t b1) {
    asm volatile(
        "mma.sync.aligned.m16n8k16.row.col.f32.bf16.bf16.f32 "
        "{%0,%1,%2,%3}, {%4,%5,%6,%7}, {%8,%9}, {%0,%1,%2,%3};"
        : "+f"(c[0]), "+f"(c[1]), "+f"(c[2]), "+f"(c[3])
        : "r"(a0), "r"(a1), "r"(a2), "r"(a3), "r"(b0), "r"(b1));
}

// 512 threads = 16 warps: 8 M-warps x 2 N-warps. Warp tile 16 rows x 64 cols.
__global__ void __launch_bounds__(512) k_gemm_mma(
    const __nv_bfloat16* __restrict__ ahi, const __nv_bfloat16* __restrict__ alo,
    const __nv_bfloat16* __restrict__ whi, const __nv_bfloat16* __restrict__ wlo,
    const float* __restrict__ alv, const float* __restrict__ arv,
    float* __restrict__ f_base, float* __restrict__ el_base, float* __restrict__ er_base) {
    extern __shared__ char smem[];
    __nv_bfloat16* Ah = (__nv_bfloat16*)smem;
    __nv_bfloat16* Al = Ah + TILEB;
    __nv_bfloat16* Bh = Al + TILEB;
    __nv_bfloat16* Bl = Bh + TILEB;
    float* s_al = (float*)(Bl + TILEB);
    float* s_ar = s_al + 128;
    uint32_t sb = smem_u32(smem);

    int tid = threadIdx.x;
    int wid = tid >> 5, lane = tid & 31;
    int wid_m = wid & 7, wid_n = wid >> 3;
    int r = blockIdx.y;
    int m0 = blockIdx.x * 128;

    float* f  = f_base  + (size_t)r * NNODES * FDIM;
    float* el = el_base + r * NNODES * 2;
    float* er = er_base + r * NNODES * 2;

    if (tid < 128) { s_al[tid] = alv[r * 128 + tid]; s_ar[tid] = arv[r * 128 + tid]; }

    // ---- cp.async fill ----
    const __nv_bfloat16* wh = whi + (size_t)r * 16384;
    const __nv_bfloat16* wl = wlo + (size_t)r * 16384;
    for (int c = tid; c < 2048; c += 512) {
        int row = c >> 4;
        int col = (c & 15) << 3;
        int gm = m0 + row;
        int sz = (gm < NNODES) ? 16 : 0;
        int gmc = (gm < NNODES) ? gm : (NNODES - 1);
        uint32_t soff = (uint32_t)(row * ASTRIDE + col) * 2;
        cp16(sb + soff,                 ahi + (size_t)gmc * 128 + col, sz);
        cp16(sb + TILEBYTES + soff,     alo + (size_t)gmc * 128 + col, sz);
        cp16(sb + 2 * TILEBYTES + soff, wh + row * 128 + col, 16);
        cp16(sb + 3 * TILEBYTES + soff, wl + row * 128 + col, 16);
    }
    asm volatile("cp.async.commit_group;");
    asm volatile("cp.async.wait_group 0;" ::: "memory");
    __syncthreads();

    // ---- MMA mainloop ----
    int m_base = wid_m * 16;
    int cb = wid_n * 64;
    float acc[8][4];
#pragma unroll
    for (int nt = 0; nt < 8; nt++)
#pragma unroll
        for (int j = 0; j < 4; j++) acc[nt][j] = 0.f;

    uint32_t a_row = (uint32_t)(m_base + (lane & 15));
    uint32_t a_colsel = (uint32_t)((lane >> 4) << 3);
    uint32_t b_row = (uint32_t)(cb + (lane & 7));
    uint32_t b_colsel = (uint32_t)(((lane >> 3) & 1) << 3);

#pragma unroll
    for (int t = 0; t < 3; t++) {
        const __nv_bfloat16* As = (t < 2) ? Ah : Al;
        const __nv_bfloat16* Bs = (t == 1) ? Bl : Bh;
        uint32_t a_base = smem_u32(As + a_row * ASTRIDE + a_colsel);
        uint32_t b_base = smem_u32(Bs + b_row * ASTRIDE + b_colsel);
#pragma unroll
        for (int kk = 0; kk < 8; kk++) {
            uint32_t a0, a1, a2, a3;
            ldsm_x4(a_base + kk * 32, a0, a1, a2, a3);
#pragma unroll
            for (int nt = 0; nt < 8; nt++) {
                uint32_t b0, b1;
                ldsm_x2(b_base + (uint32_t)(nt * 8 * ASTRIDE * 2) + kk * 32, b0, b1);
                mma16816(acc[nt], a0, a1, a2, a3, b0, b1);
            }
        }
    }

    // ---- epilogue: fused el/er (head = wid_n, warp-local) + f stores ----
    int q = lane & 3;
    int r0 = m_base + (lane >> 2);
    int r1 = r0 + 8;
    int gm0 = m0 + r0, gm1 = m0 + r1;
    float elA = 0.f, erA = 0.f, elB = 0.f, erB = 0.f;
#pragma unroll
    for (int nt = 0; nt < 8; nt++) {
        int c0 = cb + nt * 8 + q * 2;
        float a0 = s_al[c0], a1 = s_al[c0 + 1];
        float b0 = s_ar[c0], b1 = s_ar[c0 + 1];
        elA += acc[nt][0] * a0 + acc[nt][1] * a1;
        elB += acc[nt][2] * a0 + acc[nt][3] * a1;
        erA += acc[nt][0] * b0 + acc[nt][1] * b1;
        erB += acc[nt][2] * b0 + acc[nt][3] * b1;
        if (gm0 < NNODES)
            *(float2*)(f + (size_t)gm0 * 128 + c0) = make_float2(acc[nt][0], acc[nt][1]);
        if (gm1 < NNODES)
            *(float2*)(f + (size_t)gm1 * 128 + c0) = make_float2(acc[nt][2], acc[nt][3]);
    }
#pragma unroll
    for (int o = 1; o <= 2; o <<= 1) {
        elA += __shfl_xor_sync(0xffffffffu, elA, o);
        erA += __shfl_xor_sync(0xffffffffu, erA, o);
        elB += __shfl_xor_sync(0xffffffffu, elB, o);
        erB += __shfl_xor_sync(0xffffffffu, erB, o);
    }
    if (q == 0) {
        if (gm0 < NNODES) { el[2 * gm0 + wid_n] = elA; er[2 * gm0 + wid_n] = erA; }
        if (gm1 < NNODES) { el[2 * gm1 + wid_n] = elB; er[2 * gm1 + wid_n] = erB; }
    }
}

#define SMEM_GEMM (4 * TILEBYTES + 2 * 128 * 4)

// ---------------- GAT aggregation + fused semantic score (2-phase staging) ----------------
// Phase A: lanes parallel over edges -> (src, w0, w1) to smem, den via warp reduce.
// Phase B: serial loop, f-gather addresses depend only on smem -> deep pipelining.
__global__ void __launch_bounds__(256) k_aggsc(
    const float* __restrict__ f_base, const float* __restrict__ el_base,
    const float* __restrict__ er_base, const float* __restrict__ bias_base,
    const float* __restrict__ w1, const float* __restrict__ bb,
    const float* __restrict__ w2, float* __restrict__ wsum,
    float* __restrict__ z_base, int do_relu) {
    int r = blockIdx.y;
    const float* f   = f_base  + (size_t)r * NNODES * FDIM;
    const float* el  = el_base + r * NNODES * 2;
    const float* er  = er_base + r * NNODES * 2;
    const float* bias = bias_base + r * 128;
    float* z = z_base + (size_t)r * NNODES * FDIM;

    __shared__ float s_w1[128 * 32];
    __shared__ float s_b1[32], s_w2[32];
    __shared__ float s_part[8];
    __shared__ int   s_src[8][CAP];
    __shared__ float s_wgt[8][2][CAP];
    for (int i = threadIdx.x; i < 128 * 32; i += 256) s_w1[i] = w1[i];
    if (threadIdx.x < 32) { s_b1[threadIdx.x] = bb[threadIdx.x]; s_w2[threadIdx.x] = w2[threadIdx.x]; }
    __syncthreads();

    int wid = threadIdx.x >> 5, lane = threadIdx.x & 31;
    int n = blockIdx.x * 8 + wid;
    int deg = g_deg[r * NNODES + n];
    const int* bkt = &g_bkt[(size_t)(r * NNODES + n) * CAP];
    float er0 = er[2 * n], er1 = er[2 * n + 1];

    // ---- phase A: per-edge weights, lane-parallel (avg deg 16 -> 1 iter) ----
    float den0 = 0.f, den1 = 0.f;
    for (int i = lane; i < deg; i += 32) {
        int s = bkt[i];
        float e0 = el[2 * s] + er0;     e0 = e0 > 0.f ? e0 : NEG_SLOPE * e0;
        float e1 = el[2 * s + 1] + er1; e1 = e1 > 0.f ? e1 : NEG_SLOPE * e1;
        float w0 = __expf(e0), w1v = __expf(e1);
        s_src[wid][i] = s;
        s_wgt[wid][0][i] = w0;
        s_wgt[wid][1][i] = w1v;
        den0 += w0; den1 += w1v;
    }
#pragma unroll
    for (int o = 16; o; o >>= 1) {
        den0 += __shfl_xor_sync(0xffffffffu, den0, o);
        den1 += __shfl_xor_sync(0xffffffffu, den1, o);
    }
    __syncwarp();

    // ---- phase B: serial accumulate, independent gathers ----
    int myh = lane >> 4;
    float4 acc = make_float4(0.f, 0.f, 0.f, 0.f);
#pragma unroll 4
    for (int i = 0; i < deg; i++) {
        int s = s_src[wid][i];
        float w = s_wgt[wid][myh][i];
        float4 fv = *(const float4*)(f + (size_t)s * 128 + lane * 4);
        acc.x += w * fv.x; acc.y += w * fv.y; acc.z += w * fv.z; acc.w += w * fv.w;
    }
    float den = myh ? den1 : den0;
    float scale = 1.f / fmaxf(den, 1e-9f);
    float4 bv = *(const float4*)(bias + lane * 4);
    float4 o;
    o.x = acc.x * scale + bv.x;
    o.y = acc.y * scale + bv.y;
    o.z = acc.z * scale + bv.z;
    o.w = acc.w * scale + bv.w;
    if (do_relu) {
        o.x = fmaxf(o.x, 0.f); o.y = fmaxf(o.y, 0.f);
        o.z = fmaxf(o.z, 0.f); o.w = fmaxf(o.w, 0.f);
    }
    *(float4*)(z + (size_t)n * 128 + lane * 4) = o;

    // ---- fused semantic score ----
    float zr[4] = {o.x, o.y, o.z, o.w};
    float sacc = 0.f;
#pragma unroll
    for (int k = 0; k < 128; k++) {
        float zv = __shfl_sync(0xffffffffu, zr[k & 3], k >> 2);
        sacc += zv * s_w1[k * 32 + lane];
    }
    float t = tanhf(sacc + s_b1[lane]) * s_w2[lane];
#pragma unroll
    for (int oo = 16; oo; oo >>= 1) t += __shfl_xor_sync(0xffffffffu, t, oo);
    if (lane == 0) s_part[wid] = t;
    __syncthreads();
    if (threadIdx.x == 0) {
        float s = 0.f;
#pragma unroll
        for (int i2 = 0; i2 < 8; i2++) s += s_part[i2];
        atomicAdd(&wsum[r], s);
    }
}

// ---------------- combine (beta inline) ----------------
__device__ __forceinline__ void beta_from_wsum(const float* ws, float& b0, float& b1, float& b2) {
    float w0 = ws[0] / NNODES, w1 = ws[1] / NNODES, w2 = ws[2] / NNODES;
    float m = fmaxf(w0, fmaxf(w1, w2));
    float e0 = __expf(w0 - m), e1 = __expf(w1 - m), e2 = __expf(w2 - m);
    float s = e0 + e1 + e2;
    b0 = e0 / s; b1 = e1 / s; b2 = e2 / s;
}

__global__ void k_combine_bf(const float* __restrict__ z, const float* __restrict__ ws,
                             __nv_bfloat16* __restrict__ hi, __nv_bfloat16* __restrict__ lo) {
    int idx = blockIdx.x * blockDim.x + threadIdx.x;
    if (idx >= NNODES * 32) return;
    float b0, b1, b2;
    beta_from_wsum(ws, b0, b1, b2);
    float4 z0 = *(const float4*)(z + (size_t)idx * 4);
    float4 z1 = *(const float4*)(z + (size_t)NNODES * 128 + (size_t)idx * 4);
    float4 z2 = *(const float4*)(z + (size_t)2 * NNODES * 128 + (size_t)idx * 4);
    float vx = b0 * z0.x + b1 * z1.x + b2 * z2.x;
    float vy = b0 * z0.y + b1 * z1.y + b2 * z2.y;
    float vz = b0 * z0.z + b1 * z1.z + b2 * z2.z;
    float vw = b0 * z0.w + b1 * z1.w + b2 * z2.w;
    __nv_bfloat16 h0 = __float2bfloat16(vx), h1 = __float2bfloat16(vy);
    __nv_bfloat16 h2 = __float2bfloat16(vz), h3 = __float2bfloat16(vw);
    ((__nv_bfloat162*)hi)[2 * idx]     = __nv_bfloat162(h0, h1);
    ((__nv_bfloat162*)hi)[2 * idx + 1] = __nv_bfloat162(h2, h3);
    ((__nv_bfloat162*)lo)[2 * idx]     = __nv_bfloat162(
        __float2bfloat16(vx - __bfloat162float(h0)), __float2bfloat16(vy - __bfloat162float(h1)));
    ((__nv_bfloat162*)lo)[2 * idx + 1] = __nv_bfloat162(
        __float2bfloat16(vz - __bfloat162float(h2)), __float2bfloat16(vw - __bfloat162float(h3)));
}

__global__ void k_combine_f32(const float* __restrict__ z, const float* __restrict__ ws,
                              float* __restrict__ out) {
    int idx = blockIdx.x * blockDim.x + threadIdx.x;
    if (idx >= NNODES * 32) return;
    float b0, b1, b2;
    beta_from_wsum(ws, b0, b1, b2);
    float4 z0 = *(const float4*)(z + (size_t)idx * 4);
    float4 z1 = *(const float4*)(z + (size_t)NNODES * 128 + (size_t)idx * 4);
    float4 z2 = *(const float4*)(z + (size_t)2 * NNODES * 128 + (size_t)idx * 4);
    float4 o;
    o.x = b0 * z0.x + b1 * z1.x + b2 * z2.x;
    o.y = b0 * z0.y + b1 * z1.y + b2 * z2.y;
    o.z = b0 * z0.z + b1 * z1.z + b2 * z2.z;
    o.w = b0 * z0.w + b1 * z1.w + b2 * z2.w;
    *(float4*)(out + (size_t)idx * 4) = o;
}

// ---------------- launch ----------------
extern "C" void kernel_launch(void* const* d_in, const int* in_sizes, int n_in,
                              void* d_out, int out_size) {
    const float* x     = (const float*)d_in[0];
    const int*   edges = (const int*)d_in[1];
    const float* W1  = (const float*)d_in[2];
    const float* al1 = (const float*)d_in[3];
    const float* ar1 = (const float*)d_in[4];
    const float* b1  = (const float*)d_in[5];
    const float* W2  = (const float*)d_in[6];
    const float* al2 = (const float*)d_in[7];
    const float* ar2 = (const float*)d_in[8];
    const float* b2  = (const float*)d_in[9];
    const float* aw1 = (const float*)d_in[10];
    const float* ab1 = (const float*)d_in[11];
    const float* aw2 = (const float*)d_in[12];
    const float* bw1 = (const float*)d_in[13];
    const float* bb1 = (const float*)d_in[14];
    const float* bw2 = (const float*)d_in[15];
    float* out = (float*)d_out;

    float *p_f, *p_z, *p_el, *p_er, *p_ws;
    int *p_deg;
    __nv_bfloat16 *p_ahi, *p_alo, *p_whi, *p_wlo;
    cudaGetSymbolAddress((void**)&p_f,  g_f);
    cudaGetSymbolAddress((void**)&p_z,  g_z);
    cudaGetSymbolAddress((void**)&p_el, g_el);
    cudaGetSymbolAddress((void**)&p_er, g_er);
    cudaGetSymbolAddress((void**)&p_ws, g_wsum);
    cudaGetSymbolAddress((void**)&p_deg, g_deg);
    cudaGetSymbolAddress((void**)&p_ahi, g_ahi);
    cudaGetSymbolAddress((void**)&p_alo, g_alo);
    cudaGetSymbolAddress((void**)&p_whi, g_whi);
    cudaGetSymbolAddress((void**)&p_wlo, g_wlo);

    cudaFuncSetAttribute(k_gemm_mma, cudaFuncAttributeMaxDynamicSharedMemorySize, SMEM_GEMM);

    cudaMemsetAsync(p_deg, 0, NREL * NNODES * sizeof(int));
    cudaMemsetAsync(p_ws, 0, 2 * NREL * sizeof(float));
    k_build<<<dim3((NEDGES / 4 + 255) / 256, NREL), 256>>>(edges);
    k_cvtW<<<(2 * NREL * FDIM * FDIM + 255) / 256, 256>>>(W1, W2, p_whi, p_wlo);
    k_cvtA<<<(NNODES * 32 + 255) / 256, 256>>>(x, p_ahi, p_alo);

    const dim3 gemm_grid((NNODES + 127) / 128, NREL);
    const dim3 agg_grid(NNODES / 8, NREL);

    // ---- layer 1 ----
    k_gemm_mma<<<gemm_grid, 512, SMEM_GEMM>>>(p_ahi, p_alo, p_whi, p_wlo,
                                              al1, ar1, p_f, p_el, p_er);
    k_aggsc<<<agg_grid, 256>>>(p_f, p_el, p_er, b1, aw1, ab1, aw2, p_ws, p_z, 1);
    k_combine_bf<<<(NNODES * 32 + 255) / 256, 256>>>(p_z, p_ws, p_ahi, p_alo);

    // ---- layer 2 ----
    k_gemm_mma<<<gemm_grid, 512, SMEM_GEMM>>>(p_ahi, p_alo,
                                              p_whi + (size_t)NREL * FDIM * FDIM,
                                              p_wlo + (size_t)NREL * FDIM * FDIM,
                                              al2, ar2, p_f, p_el, p_er);
    k_aggsc<<<agg_grid, 256>>>(p_f, p_el, p_er, b2, bw1, bb1, bw2, p_ws + NREL, p_z, 0);
    k_combine_f32<<<(NNODES * 32 + 255) / 256, 256>>>(p_z, p_ws + NREL, out);
}

// round 15
// speedup vs baseline: 1.0996x; 1.0200x over previous
#include <cuda_runtime.h>
#include <cuda_bf16.h>
#include <cuda_fp16.h>
#include <cstdint>
#include <math.h>

#define NNODES 20000
#define NEDGES 320000
#define NREL 3
#define FDIM 128
#define NEG_SLOPE 0.2f
#define CAP 96          // bucket capacity per (relation, dst)

// ---------------- scratch (static device globals; no allocation) ----------------
__device__ __half g_fh[(size_t)NREL * NNODES * FDIM];   // f in fp16 (gather payload)
__device__ float g_z[(size_t)NREL * NNODES * FDIM];
__device__ float g_el[NREL * NNODES * 2];
__device__ float g_er[NREL * NNODES * 2];
__device__ int   g_deg[NREL * NNODES];
__device__ int   g_bkt[(size_t)NREL * NNODES * CAP];
__device__ float g_wsum[2 * NREL];
// bf16 split operands
__device__ __nv_bfloat16 g_ahi[(size_t)NNODES * FDIM];
__device__ __nv_bfloat16 g_alo[(size_t)NNODES * FDIM];
__device__ __nv_bfloat16 g_whi[2 * NREL * FDIM * FDIM];   // [layer][r][n][k]
__device__ __nv_bfloat16 g_wlo[2 * NREL * FDIM * FDIM];

// ---------------- fused bucket build (hist + scatter, 4-edge ILP) ----------------
__global__ void k_build(const int* __restrict__ edges) {
    int r = blockIdx.y;
    int t = blockIdx.x * blockDim.x + threadIdx.x;
    if (t >= NEDGES / 4) return;
    const int4 s4 = *(const int4*)(edges + (size_t)(r * 2 + 0) * NEDGES + 4 * t);
    const int4 d4 = *(const int4*)(edges + (size_t)(r * 2 + 1) * NEDGES + 4 * t);
    int base = r * NNODES;
    int p0 = atomicAdd(&g_deg[base + d4.x], 1);
    int p1 = atomicAdd(&g_deg[base + d4.y], 1);
    int p2 = atomicAdd(&g_deg[base + d4.z], 1);
    int p3 = atomicAdd(&g_deg[base + d4.w], 1);
    g_bkt[(size_t)(base + d4.x) * CAP + p0] = s4.x;
    g_bkt[(size_t)(base + d4.y) * CAP + p1] = s4.y;
    g_bkt[(size_t)(base + d4.z) * CAP + p2] = s4.z;
    g_bkt[(size_t)(base + d4.w) * CAP + p3] = s4.w;
}

// ---------------- bf16 split conversion ----------------
__global__ void k_cvtA(const float* __restrict__ src,
                       __nv_bfloat16* __restrict__ hi, __nv_bfloat16* __restrict__ lo) {
    int i = blockIdx.x * blockDim.x + threadIdx.x;
    if (i >= NNODES * 32) return;
    float4 v = ((const float4*)src)[i];
    __nv_bfloat16 h0 = __float2bfloat16(v.x), h1 = __float2bfloat16(v.y);
    __nv_bfloat16 h2 = __float2bfloat16(v.z), h3 = __float2bfloat16(v.w);
    ((__nv_bfloat162*)hi)[2 * i]     = __nv_bfloat162(h0, h1);
    ((__nv_bfloat162*)hi)[2 * i + 1] = __nv_bfloat162(h2, h3);
    ((__nv_bfloat162*)lo)[2 * i]     = __nv_bfloat162(
        __float2bfloat16(v.x - __bfloat162float(h0)), __float2bfloat16(v.y - __bfloat162float(h1)));
    ((__nv_bfloat162*)lo)[2 * i + 1] = __nv_bfloat162(
        __float2bfloat16(v.z - __bfloat162float(h2)), __float2bfloat16(v.w - __bfloat162float(h3)));
}

__global__ void k_cvtW(const float* __restrict__ W1, const float* __restrict__ W2,
                       __nv_bfloat16* __restrict__ hi, __nv_bfloat16* __restrict__ lo) {
    int idx = blockIdx.x * blockDim.x + threadIdx.x;
    if (idx >= 2 * NREL * FDIM * FDIM) return;
    int l = idx / (NREL * FDIM * FDIM);
    int rem = idx - l * (NREL * FDIM * FDIM);
    int r = rem >> 14;
    int n = (rem >> 7) & 127, k = rem & 127;
    const float* W = l ? W2 : W1;
    float v = W[r * 16384 + k * 128 + n];
    __nv_bfloat16 h = __float2bfloat16(v);
    hi[idx] = h;
    lo[idx] = __float2bfloat16(v - __bfloat162float(h));
}

// ---------------- mma.sync GEMM (round-8 structure; fp16 f stores) ----------------
#define ASTRIDE 136
#define TILEB  (128 * ASTRIDE)
#define TILEBYTES (TILEB * 2)

__device__ __forceinline__ uint32_t smem_u32(const void* p) {
    uint32_t a;
    asm("{ .reg .u64 t; cvta.to.shared.u64 t, %1; cvt.u32.u64 %0, t; }" : "=r"(a) : "l"(p));
    return a;
}
__device__ __forceinline__ void cp16(uint32_t dst, const void* src, int sz) {
    asm volatile("cp.async.cg.shared.global [%0], [%1], 16, %2;"
                 :: "r"(dst), "l"(src), "r"(sz));
}
__device__ __forceinline__ void ldsm_x4(uint32_t addr, uint32_t& r0, uint32_t& r1,
                                        uint32_t& r2, uint32_t& r3) {
    asm volatile("ldmatrix.sync.aligned.m8n8.x4.shared.b16 {%0,%1,%2,%3}, [%4];"
                 : "=r"(r0), "=r"(r1), "=r"(r2), "=r"(r3) : "r"(addr));
}
__device__ __forceinline__ void ldsm_x2(uint32_t addr, uint32_t& r0, uint32_t& r1) {
    asm volatile("ldmatrix.sync.aligned.m8n8.x2.shared.b16 {%0,%1}, [%2];"
                 : "=r"(r0), "=r"(r1) : "r"(addr));
}
__device__ __forceinline__ void mma16816(float* c, uint32_t a0, uint32_t a1, uint32_t a2,
                                         uint32_t a3, uint32_t b0, uint32_t b1) {
    asm volatile(
        "mma.sync.aligned.m16n8k16.row.col.f32.bf16.bf16.f32 "
        "{%0,%1,%2,%3}, {%4,%5,%6,%7}, {%8,%9}, {%0,%1,%2,%3};"
        : "+f"(c[0]), "+f"(c[1]), "+f"(c[2]), "+f"(c[3])
        : "r"(a0), "r"(a1), "r"(a2), "r"(a3), "r"(b0), "r"(b1));
}

// 512 threads = 16 warps: 8 M-warps x 2 N-warps. Warp tile 16 rows x 64 cols.
__global__ void __launch_bounds__(512) k_gemm_mma(
    const __nv_bfloat16* __restrict__ ahi, const __nv_bfloat16* __restrict__ alo,
    const __nv_bfloat16* __restrict__ whi, const __nv_bfloat16* __restrict__ wlo,
    const float* __restrict__ alv, const float* __restrict__ arv,
    __half* __restrict__ fh_base, float* __restrict__ el_base, float* __restrict__ er_base) {
    extern __shared__ char smem[];
    __nv_bfloat16* Ah = (__nv_bfloat16*)smem;
    __nv_bfloat16* Al = Ah + TILEB;
    __nv_bfloat16* Bh = Al + TILEB;
    __nv_bfloat16* Bl = Bh + TILEB;
    float* s_al = (float*)(Bl + TILEB);
    float* s_ar = s_al + 128;
    uint32_t sb = smem_u32(smem);

    int tid = threadIdx.x;
    int wid = tid >> 5, lane = tid & 31;
    int wid_m = wid & 7, wid_n = wid >> 3;
    int r = blockIdx.y;
    int m0 = blockIdx.x * 128;

    __half* fh = fh_base + (size_t)r * NNODES * FDIM;
    float* el = el_base + r * NNODES * 2;
    float* er = er_base + r * NNODES * 2;

    if (tid < 128) { s_al[tid] = alv[r * 128 + tid]; s_ar[tid] = arv[r * 128 + tid]; }

    // ---- cp.async fill ----
    const __nv_bfloat16* wh = whi + (size_t)r * 16384;
    const __nv_bfloat16* wl = wlo + (size_t)r * 16384;
    for (int c = tid; c < 2048; c += 512) {
        int row = c >> 4;
        int col = (c & 15) << 3;
        int gm = m0 + row;
        int sz = (gm < NNODES) ? 16 : 0;
        int gmc = (gm < NNODES) ? gm : (NNODES - 1);
        uint32_t soff = (uint32_t)(row * ASTRIDE + col) * 2;
        cp16(sb + soff,                 ahi + (size_t)gmc * 128 + col, sz);
        cp16(sb + TILEBYTES + soff,     alo + (size_t)gmc * 128 + col, sz);
        cp16(sb + 2 * TILEBYTES + soff, wh + row * 128 + col, 16);
        cp16(sb + 3 * TILEBYTES + soff, wl + row * 128 + col, 16);
    }
    asm volatile("cp.async.commit_group;");
    asm volatile("cp.async.wait_group 0;" ::: "memory");
    __syncthreads();

    // ---- MMA mainloop ----
    int m_base = wid_m * 16;
    int cb = wid_n * 64;
    float acc[8][4];
#pragma unroll
    for (int nt = 0; nt < 8; nt++)
#pragma unroll
        for (int j = 0; j < 4; j++) acc[nt][j] = 0.f;

    uint32_t a_row = (uint32_t)(m_base + (lane & 15));
    uint32_t a_colsel = (uint32_t)((lane >> 4) << 3);
    uint32_t b_row = (uint32_t)(cb + (lane & 7));
    uint32_t b_colsel = (uint32_t)(((lane >> 3) & 1) << 3);

#pragma unroll
    for (int t = 0; t < 3; t++) {
        const __nv_bfloat16* As = (t < 2) ? Ah : Al;
        const __nv_bfloat16* Bs = (t == 1) ? Bl : Bh;
        uint32_t a_base = smem_u32(As + a_row * ASTRIDE + a_colsel);
        uint32_t b_base = smem_u32(Bs + b_row * ASTRIDE + b_colsel);
#pragma unroll
        for (int kk = 0; kk < 8; kk++) {
            uint32_t a0, a1, a2, a3;
            ldsm_x4(a_base + kk * 32, a0, a1, a2, a3);
#pragma unroll
            for (int nt = 0; nt < 8; nt++) {
                uint32_t b0, b1;
                ldsm_x2(b_base + (uint32_t)(nt * 8 * ASTRIDE * 2) + kk * 32, b0, b1);
                mma16816(acc[nt], a0, a1, a2, a3, b0, b1);
            }
        }
    }

    // ---- epilogue: fused el/er (head = wid_n, warp-local) + fp16 f stores ----
    int q = lane & 3;
    int r0 = m_base + (lane >> 2);
    int r1 = r0 + 8;
    int gm0 = m0 + r0, gm1 = m0 + r1;
    float elA = 0.f, erA = 0.f, elB = 0.f, erB = 0.f;
#pragma unroll
    for (int nt = 0; nt < 8; nt++) {
        int c0 = cb + nt * 8 + q * 2;
        float a0 = s_al[c0], a1 = s_al[c0 + 1];
        float b0 = s_ar[c0], b1 = s_ar[c0 + 1];
        elA += acc[nt][0] * a0 + acc[nt][1] * a1;
        elB += acc[nt][2] * a0 + acc[nt][3] * a1;
        erA += acc[nt][0] * b0 + acc[nt][1] * b1;
        erB += acc[nt][2] * b0 + acc[nt][3] * b1;
        if (gm0 < NNODES)
            *(__half2*)(fh + (size_t)gm0 * 128 + c0) =
                __float22half2_rn(make_float2(acc[nt][0], acc[nt][1]));
        if (gm1 < NNODES)
            *(__half2*)(fh + (size_t)gm1 * 128 + c0) =
                __float22half2_rn(make_float2(acc[nt][2], acc[nt][3]));
    }
#pragma unroll
    for (int o = 1; o <= 2; o <<= 1) {
        elA += __shfl_xor_sync(0xffffffffu, elA, o);
        erA += __shfl_xor_sync(0xffffffffu, erA, o);
        elB += __shfl_xor_sync(0xffffffffu, elB, o);
        erB += __shfl_xor_sync(0xffffffffu, erB, o);
    }
    if (q == 0) {
        if (gm0 < NNODES) { el[2 * gm0 + wid_n] = elA; er[2 * gm0 + wid_n] = erA; }
        if (gm1 < NNODES) { el[2 * gm1 + wid_n] = elB; er[2 * gm1 + wid_n] = erB; }
    }
}

#define SMEM_GEMM (4 * TILEBYTES + 2 * 128 * 4)

// ---------------- GAT aggregation + fused semantic score (fp16 f gathers) ----------------
__global__ void __launch_bounds__(256) k_aggsc(
    const __half* __restrict__ fh_base, const float* __restrict__ el_base,
    const float* __restrict__ er_base, const float* __restrict__ bias_base,
    const float* __restrict__ w1, const float* __restrict__ bb,
    const float* __restrict__ w2, float* __restrict__ wsum,
    float* __restrict__ z_base, int do_relu) {
    int r = blockIdx.y;
    const __half* fh = fh_base + (size_t)r * NNODES * FDIM;
    const float* el  = el_base + r * NNODES * 2;
    const float* er  = er_base + r * NNODES * 2;
    const float* bias = bias_base + r * 128;
    float* z = z_base + (size_t)r * NNODES * FDIM;

    __shared__ float s_w1[128 * 32];
    __shared__ float s_b1[32], s_w2[32];
    __shared__ float s_part[8];
    __shared__ int   s_src[8][CAP];
    __shared__ float s_wgt[8][2][CAP];
    for (int i = threadIdx.x; i < 128 * 32; i += 256) s_w1[i] = w1[i];
    if (threadIdx.x < 32) { s_b1[threadIdx.x] = bb[threadIdx.x]; s_w2[threadIdx.x] = w2[threadIdx.x]; }
    __syncthreads();

    int wid = threadIdx.x >> 5, lane = threadIdx.x & 31;
    int n = blockIdx.x * 8 + wid;
    int deg = g_deg[r * NNODES + n];
    const int* bkt = &g_bkt[(size_t)(r * NNODES + n) * CAP];
    float er0 = er[2 * n], er1 = er[2 * n + 1];

    // ---- phase A: per-edge weights, lane-parallel ----
    float den0 = 0.f, den1 = 0.f;
    for (int i = lane; i < deg; i += 32) {
        int s = bkt[i];
        float2 ev = *(const float2*)(el + 2 * s);
        float e0 = ev.x + er0; e0 = e0 > 0.f ? e0 : NEG_SLOPE * e0;
        float e1 = ev.y + er1; e1 = e1 > 0.f ? e1 : NEG_SLOPE * e1;
        float w0 = __expf(e0), w1v = __expf(e1);
        s_src[wid][i] = s;
        s_wgt[wid][0][i] = w0;
        s_wgt[wid][1][i] = w1v;
        den0 += w0; den1 += w1v;
    }
#pragma unroll
    for (int o = 16; o; o >>= 1) {
        den0 += __shfl_xor_sync(0xffffffffu, den0, o);
        den1 += __shfl_xor_sync(0xffffffffu, den1, o);
    }
    __syncwarp();

    // ---- phase B: serial accumulate, 8B fp16 gathers ----
    int myh = lane >> 4;
    float4 acc = make_float4(0.f, 0.f, 0.f, 0.f);
#pragma unroll 4
    for (int i = 0; i < deg; i++) {
        int s = s_src[wid][i];
        float w = s_wgt[wid][myh][i];
        uint2 raw = *(const uint2*)(fh + (size_t)s * 128 + lane * 4);
        float2 a = __half22float2(*(const __half2*)&raw.x);
        float2 b = __half22float2(*(const __half2*)&raw.y);
        acc.x += w * a.x; acc.y += w * a.y; acc.z += w * b.x; acc.w += w * b.y;
    }
    float den = myh ? den1 : den0;
    float scale = 1.f / fmaxf(den, 1e-9f);
    float4 bv = *(const float4*)(bias + lane * 4);
    float4 o;
    o.x = acc.x * scale + bv.x;
    o.y = acc.y * scale + bv.y;
    o.z = acc.z * scale + bv.z;
    o.w = acc.w * scale + bv.w;
    if (do_relu) {
        o.x = fmaxf(o.x, 0.f); o.y = fmaxf(o.y, 0.f);
        o.z = fmaxf(o.z, 0.f); o.w = fmaxf(o.w, 0.f);
    }
    *(float4*)(z + (size_t)n * 128 + lane * 4) = o;

    // ---- fused semantic score ----
    float zr[4] = {o.x, o.y, o.z, o.w};
    float sacc = 0.f;
#pragma unroll
    for (int k = 0; k < 128; k++) {
        float zv = __shfl_sync(0xffffffffu, zr[k & 3], k >> 2);
        sacc += zv * s_w1[k * 32 + lane];
    }
    float t = tanhf(sacc + s_b1[lane]) * s_w2[lane];
#pragma unroll
    for (int oo = 16; oo; oo >>= 1) t += __shfl_xor_sync(0xffffffffu, t, oo);
    if (lane == 0) s_part[wid] = t;
    __syncthreads();
    if (threadIdx.x == 0) {
        float s = 0.f;
#pragma unroll
        for (int i2 = 0; i2 < 8; i2++) s += s_part[i2];
        atomicAdd(&wsum[r], s);
    }
}

// ---------------- combine (beta inline) ----------------
__device__ __forceinline__ void beta_from_wsum(const float* ws, float& b0, float& b1, float& b2) {
    float w0 = ws[0] / NNODES, w1 = ws[1] / NNODES, w2 = ws[2] / NNODES;
    float m = fmaxf(w0, fmaxf(w1, w2));
    float e0 = __expf(w0 - m), e1 = __expf(w1 - m), e2 = __expf(w2 - m);
    float s = e0 + e1 + e2;
    b0 = e0 / s; b1 = e1 / s; b2 = e2 / s;
}

__global__ void k_combine_bf(const float* __restrict__ z, const float* __restrict__ ws,
                             __nv_bfloat16* __restrict__ hi, __nv_bfloat16* __restrict__ lo) {
    int idx = blockIdx.x * blockDim.x + threadIdx.x;
    if (idx >= NNODES * 32) return;
    float b0, b1, b2;
    beta_from_wsum(ws, b0, b1, b2);
    float4 z0 = *(const float4*)(z + (size_t)idx * 4);
    float4 z1 = *(const float4*)(z + (size_t)NNODES * 128 + (size_t)idx * 4);
    float4 z2 = *(const float4*)(z + (size_t)2 * NNODES * 128 + (size_t)idx * 4);
    float vx = b0 * z0.x + b1 * z1.x + b2 * z2.x;
    float vy = b0 * z0.y + b1 * z1.y + b2 * z2.y;
    float vz = b0 * z0.z + b1 * z1.z + b2 * z2.z;
    float vw = b0 * z0.w + b1 * z1.w + b2 * z2.w;
    __nv_bfloat16 h0 = __float2bfloat16(vx), h1 = __float2bfloat16(vy);
    __nv_bfloat16 h2 = __float2bfloat16(vz), h3 = __float2bfloat16(vw);
    ((__nv_bfloat162*)hi)[2 * idx]     = __nv_bfloat162(h0, h1);
    ((__nv_bfloat162*)hi)[2 * idx + 1] = __nv_bfloat162(h2, h3);
    ((__nv_bfloat162*)lo)[2 * idx]     = __nv_bfloat162(
        __float2bfloat16(vx - __bfloat162float(h0)), __float2bfloat16(vy - __bfloat162float(h1)));
    ((__nv_bfloat162*)lo)[2 * idx + 1] = __nv_bfloat162(
        __float2bfloat16(vz - __bfloat162float(h2)), __float2bfloat16(vw - __bfloat162float(h3)));
}

__global__ void k_combine_f32(const float* __restrict__ z, const float* __restrict__ ws,
                              float* __restrict__ out) {
    int idx = blockIdx.x * blockDim.x + threadIdx.x;
    if (idx >= NNODES * 32) return;
    float b0, b1, b2;
    beta_from_wsum(ws, b0, b1, b2);
    float4 z0 = *(const float4*)(z + (size_t)idx * 4);
    float4 z1 = *(const float4*)(z + (size_t)NNODES * 128 + (size_t)idx * 4);
    float4 z2 = *(const float4*)(z + (size_t)2 * NNODES * 128 + (size_t)idx * 4);
    float4 o;
    o.x = b0 * z0.x + b1 * z1.x + b2 * z2.x;
    o.y = b0 * z0.y + b1 * z1.y + b2 * z2.y;
    o.z = b0 * z0.z + b1 * z1.z + b2 * z2.z;
    o.w = b0 * z0.w + b1 * z1.w + b2 * z2.w;
    *(float4*)(out + (size_t)idx * 4) = o;
}

// ---------------- launch ----------------
extern "C" void kernel_launch(void* const* d_in, const int* in_sizes, int n_in,
                              void* d_out, int out_size) {
    const float* x     = (const float*)d_in[0];
    const int*   edges = (const int*)d_in[1];
    const float* W1  = (const float*)d_in[2];
    const float* al1 = (const float*)d_in[3];
    const float* ar1 = (const float*)d_in[4];
    const float* b1  = (const float*)d_in[5];
    const float* W2  = (const float*)d_in[6];
    const float* al2 = (const float*)d_in[7];
    const float* ar2 = (const float*)d_in[8];
    const float* b2  = (const float*)d_in[9];
    const float* aw1 = (const float*)d_in[10];
    const float* ab1 = (const float*)d_in[11];
    const float* aw2 = (const float*)d_in[12];
    const float* bw1 = (const float*)d_in[13];
    const float* bb1 = (const float*)d_in[14];
    const float* bw2 = (const float*)d_in[15];
    float* out = (float*)d_out;

    float *p_z, *p_el, *p_er, *p_ws;
    __half* p_fh;
    int *p_deg;
    __nv_bfloat16 *p_ahi, *p_alo, *p_whi, *p_wlo;
    cudaGetSymbolAddress((void**)&p_fh, g_fh);
    cudaGetSymbolAddress((void**)&p_z,  g_z);
    cudaGetSymbolAddress((void**)&p_el, g_el);
    cudaGetSymbolAddress((void**)&p_er, g_er);
    cudaGetSymbolAddress((void**)&p_ws, g_wsum);
    cudaGetSymbolAddress((void**)&p_deg, g_deg);
    cudaGetSymbolAddress((void**)&p_ahi, g_ahi);
    cudaGetSymbolAddress((void**)&p_alo, g_alo);
    cudaGetSymbolAddress((void**)&p_whi, g_whi);
    cudaGetSymbolAddress((void**)&p_wlo, g_wlo);

    cudaFuncSetAttribute(k_gemm_mma, cudaFuncAttributeMaxDynamicSharedMemorySize, SMEM_GEMM);

    cudaMemsetAsync(p_deg, 0, NREL * NNODES * sizeof(int));
    cudaMemsetAsync(p_ws, 0, 2 * NREL * sizeof(float));
    k_build<<<dim3((NEDGES / 4 + 255) / 256, NREL), 256>>>(edges);
    k_cvtW<<<(2 * NREL * FDIM * FDIM + 255) / 256, 256>>>(W1, W2, p_whi, p_wlo);
    k_cvtA<<<(NNODES * 32 + 255) / 256, 256>>>(x, p_ahi, p_alo);

    const dim3 gemm_grid((NNODES + 127) / 128, NREL);
    const dim3 agg_grid(NNODES / 8, NREL);

    // ---- layer 1 ----
    k_gemm_mma<<<gemm_grid, 512, SMEM_GEMM>>>(p_ahi, p_alo, p_whi, p_wlo,
                                              al1, ar1, p_fh, p_el, p_er);
    k_aggsc<<<agg_grid, 256>>>(p_fh, p_el, p_er, b1, aw1, ab1, aw2, p_ws, p_z, 1);
    k_combine_bf<<<(NNODES * 32 + 255) / 256, 256>>>(p_z, p_ws, p_ahi, p_alo);

    // ---- layer 2 ----
    k_gemm_mma<<<gemm_grid, 512, SMEM_GEMM>>>(p_ahi, p_alo,
                                              p_whi + (size_t)NREL * FDIM * FDIM,
                                              p_wlo + (size_t)NREL * FDIM * FDIM,
                                              al2, ar2, p_fh, p_el, p_er);
    k_aggsc<<<agg_grid, 256>>>(p_fh, p_el, p_er, b2, bw1, bb1, bw2, p_ws + NREL, p_z, 0);
    k_combine_f32<<<(NNODES * 32 + 255) / 256, 256>>>(p_z, p_ws + NREL, out);
}